// round 6
// baseline (speedup 1.0000x reference)
#include <cuda_runtime.h>
#include <cstdint>

#define BB  2048
#define IN  512
#define NF  256
#define NP  256
#define EPS 1e-8f

// ---------------------------------------------------------------------------
// Device globals (allocation-free rule)
// ---------------------------------------------------------------------------
__device__ float g_xsigT[NF * BB];     // [f][b] sigmoid(x @ W^T), f-major
__device__ float g_psigT[NF * NP];     // [f][p] sigmoid(prototypes), f-major
__device__ float g_SxP[4 * BB];        // partial row sums of x_sig (per f-tile)
__device__ float g_Sp[NP];             // full row sums of p_sig

__device__ __forceinline__ float sigmoidf(float v) {
    return 1.0f / (1.0f + __expf(-v));
}

__device__ __forceinline__ uint32_t smem_u32(const void* p) {
    uint32_t a;
    asm("{ .reg .u64 t; cvta.to.shared.u64 t, %1; cvt.u32.u64 %0, t; }"
        : "=r"(a) : "l"(p));
    return a;
}

__device__ __forceinline__ uint32_t tf32r(float v) {
    uint32_t u;
    asm("cvt.rna.tf32.f32 %0, %1;" : "=r"(u) : "f"(v));
    return u;
}

__device__ __forceinline__ void ldsm_x4(uint32_t& r0, uint32_t& r1,
                                        uint32_t& r2, uint32_t& r3, uint32_t addr) {
    asm volatile("ldmatrix.sync.aligned.m8n8.x4.shared.b16 {%0,%1,%2,%3}, [%4];"
                 : "=r"(r0), "=r"(r1), "=r"(r2), "=r"(r3) : "r"(addr));
}

__device__ __forceinline__ void mma_tf32(float* d, const uint32_t* a, const uint32_t* b) {
    asm volatile(
        "mma.sync.aligned.m16n8k8.row.col.f32.tf32.tf32.f32 "
        "{%0,%1,%2,%3}, {%4,%5,%6,%7}, {%8,%9}, {%0,%1,%2,%3};"
        : "+f"(d[0]), "+f"(d[1]), "+f"(d[2]), "+f"(d[3])
        : "r"(a[0]), "r"(a[1]), "r"(a[2]), "r"(a[3]), "r"(b[0]), "r"(b[1]));
}

// ---------------------------------------------------------------------------
// Fused Kernel: GEMM CTAs (blockIdx.x < 32) + prototype CTAs (blockIdx.x == 32)
//
// GEMM: x (B x IN) @ features^T (NF x IN) -> sigmoid -> g_xsigT [f][b] + SxP.
//   CTA tile 64(b) x 64(f), 256 threads (8 warps, 32x16 warp tiles).
//   K chunks of 32, double-buffered smem.
// PROTO: 4 CTAs, each 64p x 256f: sigmoid(prototypes) -> g_psigT [f][p] + Sp.
// grid (33, 4) = 132 CTAs (one wave on 148 SMs), 256 threads.
// ---------------------------------------------------------------------------
#define KC      32
#define ASTR    36                      // smem row stride in floats (144B)
#define TILE_FL (64 * ASTR)             // floats per buffer

__global__ void __launch_bounds__(256, 1)
feat_gemm_kernel(const float* __restrict__ x,
                 const float* __restrict__ features,
                 const float* __restrict__ prototypes) {
    __shared__ __align__(16) float As[2][TILE_FL];
    __shared__ __align__(16) float Bs[2][TILE_FL];

    const int tid  = threadIdx.x;

    // ======================= prototype path =======================
    if (blockIdx.x == 32) {
        float (*t)[65] = (float(*)[65])&As[0][0];     // 64 x 65 tile (16.6 KB)
        const int p0 = blockIdx.y * 64;
        float spacc = 0.f;

        for (int fc = 0; fc < 4; fc++) {
            #pragma unroll
            for (int i = 0; i < 16; i++) {
                int idx = tid + i * 256;              // 0..4095
                int p = idx >> 6, f = idx & 63;
                t[p][f] = sigmoidf(prototypes[(size_t)(p0 + p) * NF + fc * 64 + f]);
            }
            __syncthreads();
            #pragma unroll
            for (int i = 0; i < 16; i++) {
                int idx = tid + i * 256;
                int f = idx >> 6, p = idx & 63;
                g_psigT[(size_t)(fc * 64 + f) * NP + p0 + p] = t[p][f];
            }
            if (tid < 64) {
                float s = 0.f;
                #pragma unroll 16
                for (int f = 0; f < 64; f++) s += t[tid][f];
                spacc += s;
            }
            __syncthreads();
        }
        if (tid < 64) g_Sp[p0 + tid] = spacc;
        return;
    }

    // ========================= GEMM path =========================
    const int wid  = tid >> 5;
    const int lane = tid & 31;
    const int b0 = blockIdx.x * 64;
    const int f0 = blockIdx.y * 64;
    const int m_off = (wid & 1) * 32;        // m in {0, 32}
    const int n_off = (wid >> 1) * 16;       // n in {0, 16, 32, 48}

    // global loader mapping: 512 float4 per operand tile, 2 per thread
    int lrow[2], lkq[2];
    #pragma unroll
    for (int i = 0; i < 2; i++) {
        int idx = tid + i * 256;
        lrow[i] = idx >> 3;                  // 0..63
        lkq[i]  = idx & 7;                   // float4 slot along k
    }

    // ldmatrix per-thread byte offsets (hardware-validated mapping)
    const uint32_t sA = smem_u32(As);
    const uint32_t sB = smem_u32(Bs);
    const uint32_t a_off = (uint32_t)(((lane & 15) + m_off) * ASTR + ((lane >> 4) & 1) * 4) * 4;
    const uint32_t b_off = (uint32_t)((((lane & 7) + ((lane >> 4) & 1) * 8) + n_off) * ASTR
                                      + ((lane >> 3) & 1) * 4) * 4;

    float4 av[2], bv[2];
    #pragma unroll
    for (int i = 0; i < 2; i++) {
        av[i] = *(const float4*)&x[(size_t)(b0 + lrow[i]) * IN + lkq[i] * 4];
        bv[i] = *(const float4*)&features[(size_t)(f0 + lrow[i]) * IN + lkq[i] * 4];
    }

    float acc[2][2][4] = {};                 // [mt][nt][4]

    for (int c = 0; c < IN / KC; c++) {
        const int buf = c & 1;

        #pragma unroll
        for (int i = 0; i < 2; i++) {
            uint4 ua = make_uint4(tf32r(av[i].x), tf32r(av[i].y), tf32r(av[i].z), tf32r(av[i].w));
            uint4 ub = make_uint4(tf32r(bv[i].x), tf32r(bv[i].y), tf32r(bv[i].z), tf32r(bv[i].w));
            *(uint4*)&As[buf][lrow[i] * ASTR + lkq[i] * 4] = ua;
            *(uint4*)&Bs[buf][lrow[i] * ASTR + lkq[i] * 4] = ub;
        }
        __syncthreads();

        if (c + 1 < IN / KC) {
            const int k0 = (c + 1) * KC;
            #pragma unroll
            for (int i = 0; i < 2; i++) {
                av[i] = *(const float4*)&x[(size_t)(b0 + lrow[i]) * IN + k0 + lkq[i] * 4];
                bv[i] = *(const float4*)&features[(size_t)(f0 + lrow[i]) * IN + k0 + lkq[i] * 4];
            }
        }

        const uint32_t baseA = sA + (uint32_t)buf * TILE_FL * 4;
        const uint32_t baseB = sB + (uint32_t)buf * TILE_FL * 4;

        #pragma unroll
        for (int s = 0; s < 4; s++) {
            const uint32_t kb = (uint32_t)(s * 8) * 4;
            uint32_t aa[2][4], bb[4];
            ldsm_x4(aa[0][0], aa[0][1], aa[0][2], aa[0][3], baseA + a_off + kb);
            ldsm_x4(aa[1][0], aa[1][1], aa[1][2], aa[1][3], baseA + a_off + kb + 16 * ASTR * 4);
            ldsm_x4(bb[0], bb[1], bb[2], bb[3], baseB + b_off + kb);
            #pragma unroll
            for (int mt = 0; mt < 2; mt++)
                #pragma unroll
                for (int nt = 0; nt < 2; nt++)
                    mma_tf32(acc[mt][nt], aa[mt], &bb[nt * 2]);
        }
        __syncthreads();
    }

    // ---- epilogue: sigmoid, transpose-stage through smem, coalesced store ----
    float* Csm = &As[0][0];                  // 64 x 68 overlay (4352 floats: fits in As)
    #define CSTR 68
    __syncthreads();

    {
        const int mrow = m_off + (lane >> 2);
        const int ncol = n_off + 2 * (lane & 3);
        #pragma unroll
        for (int mt = 0; mt < 2; mt++) {
            #pragma unroll
            for (int nt = 0; nt < 2; nt++) {
                const int m = mrow + mt * 16;
                const int n = ncol + nt * 8;
                Csm[(n    ) * CSTR + m    ] = sigmoidf(acc[mt][nt][0]);
                Csm[(n + 1) * CSTR + m    ] = sigmoidf(acc[mt][nt][1]);
                Csm[(n    ) * CSTR + m + 8] = sigmoidf(acc[mt][nt][2]);
                Csm[(n + 1) * CSTR + m + 8] = sigmoidf(acc[mt][nt][3]);
            }
        }
    }
    __syncthreads();

    // write g_xsigT: 64 f-rows x 16 float4 (1024 float4, 4 per thread)
    #pragma unroll
    for (int i = 0; i < 4; i++) {
        int idx = tid + i * 256;             // 0..1023
        int f = idx >> 4;
        int q = idx & 15;
        float4 v = *(float4*)&Csm[f * CSTR + q * 4];
        *(float4*)&g_xsigT[(size_t)(f0 + f) * BB + b0 + q * 4] = v;
    }

    // Sx partials: threads 0..63 sum their b-column over this CTA's 64 f's
    if (tid < 64) {
        float s = 0.f;
        #pragma unroll 16
        for (int f = 0; f < 64; f++) s += Csm[f * CSTR + tid];
        g_SxP[blockIdx.y * BB + b0 + tid] = s;
    }
}

// ---------------------------------------------------------------------------
// Kernel C: Tversky core.
// I[b,p] = sum_f min(xs, ps);  out = I / (I + a*(Sx-I) + b*(Sp-I) + eps) + bias
// 64(b) x 64(p) tile, 256 threads, 4x4 per thread.  grid (32, 4).
// ---------------------------------------------------------------------------
__global__ void tversky_kernel(const float* __restrict__ bias,
                               const float* __restrict__ alphap,
                               const float* __restrict__ betap,
                               float* __restrict__ out) {
    __shared__ float xs[32][64];   // [f][b]
    __shared__ float ps[32][64];   // [f][p]

    const int tid = threadIdx.x;
    const int tx = tid & 15;       // p direction (x4)
    const int ty = tid >> 4;       // b direction (x4)
    const int b0 = blockIdx.x * 64;
    const int p0 = blockIdx.y * 64;

    float acc[4][4] = {};

    for (int f0 = 0; f0 < NF; f0 += 32) {
        #pragma unroll
        for (int i = 0; i < 2; i++) {
            int idx = tid + i * 256;
            int fr  = idx >> 4;
            int bc  = (idx & 15) * 4;
            *(float4*)&xs[fr][bc] = *(const float4*)&g_xsigT[(size_t)(f0 + fr) * BB + b0 + bc];
            *(float4*)&ps[fr][bc] = *(const float4*)&g_psigT[(size_t)(f0 + fr) * NP + p0 + bc];
        }
        __syncthreads();

        #pragma unroll 8
        for (int k = 0; k < 32; k++) {
            float4 a = *(const float4*)&xs[k][ty * 4];
            float4 p = *(const float4*)&ps[k][tx * 4];
            float av[4] = {a.x, a.y, a.z, a.w};
            float pv[4] = {p.x, p.y, p.z, p.w};
            #pragma unroll
            for (int i = 0; i < 4; i++)
                #pragma unroll
                for (int j = 0; j < 4; j++)
                    acc[i][j] += fminf(av[i], pv[j]);
        }
        __syncthreads();
    }

    const float alpha = *alphap;
    const float beta  = *betap;

    float bi[4], spv[4];
    #pragma unroll
    for (int j = 0; j < 4; j++) {
        int p = p0 + tx * 4 + j;
        bi[j]  = bias[p];
        spv[j] = g_Sp[p];
    }

    #pragma unroll
    for (int i = 0; i < 4; i++) {
        int b = b0 + ty * 4 + i;
        float Sx = g_SxP[b] + g_SxP[BB + b] + g_SxP[2 * BB + b] + g_SxP[3 * BB + b];
        float4 o;
        float r[4];
        #pragma unroll
        for (int j = 0; j < 4; j++) {
            float I = acc[i][j];
            float denom = I + alpha * (Sx - I) + beta * (spv[j] - I) + EPS;
            r[j] = I / denom + bi[j];
        }
        o.x = r[0]; o.y = r[1]; o.z = r[2]; o.w = r[3];
        *(float4*)&out[(size_t)b * NP + p0 + tx * 4] = o;
    }
}

// ---------------------------------------------------------------------------
// Launch. Inputs: x, features, prototypes, bias, alpha, beta.
// ---------------------------------------------------------------------------
extern "C" void kernel_launch(void* const* d_in, const int* in_sizes, int n_in,
                              void* d_out, int out_size) {
    const float* x          = (const float*)d_in[0];
    const float* features   = (const float*)d_in[1];
    const float* prototypes = (const float*)d_in[2];
    const float* bias       = (const float*)d_in[3];
    const float* alpha      = (const float*)d_in[4];
    const float* beta       = (const float*)d_in[5];
    float* out = (float*)d_out;

    feat_gemm_kernel<<<dim3(33, 4), 256>>>(x, features, prototypes);
    tversky_kernel<<<dim3(BB / 64, NP / 64), 256>>>(bias, alpha, beta, out);
}

// round 7
// speedup vs baseline: 1.0180x; 1.0180x over previous
#include <cuda_runtime.h>
#include <cstdint>

#define BB  2048
#define IN  512
#define NF  256
#define NP  256
#define EPS 1e-8f

// ---------------------------------------------------------------------------
// Device globals (allocation-free rule)
// ---------------------------------------------------------------------------
__device__ float g_xsigT[NF * BB];     // [f][b] sigmoid(x @ W^T), f-major
__device__ float g_psigT[NF * NP];     // [f][p] sigmoid(prototypes), f-major
__device__ float g_SxP[4 * BB];        // partial row sums of x_sig (per f-tile)
__device__ float g_Sp[NP];             // full row sums of p_sig

__device__ __forceinline__ float sigmoidf(float v) {
    return 1.0f / (1.0f + __expf(-v));
}

__device__ __forceinline__ uint32_t smem_u32(const void* p) {
    uint32_t a;
    asm("{ .reg .u64 t; cvta.to.shared.u64 t, %1; cvt.u32.u64 %0, t; }"
        : "=r"(a) : "l"(p));
    return a;
}

__device__ __forceinline__ uint32_t tf32r(float v) {
    uint32_t u;
    asm("cvt.rna.tf32.f32 %0, %1;" : "=r"(u) : "f"(v));
    return u;
}

__device__ __forceinline__ void ldsm_x4(uint32_t& r0, uint32_t& r1,
                                        uint32_t& r2, uint32_t& r3, uint32_t addr) {
    asm volatile("ldmatrix.sync.aligned.m8n8.x4.shared.b16 {%0,%1,%2,%3}, [%4];"
                 : "=r"(r0), "=r"(r1), "=r"(r2), "=r"(r3) : "r"(addr));
}

__device__ __forceinline__ void mma_tf32(float* d, const uint32_t* a, const uint32_t* b) {
    asm volatile(
        "mma.sync.aligned.m16n8k8.row.col.f32.tf32.tf32.f32 "
        "{%0,%1,%2,%3}, {%4,%5,%6,%7}, {%8,%9}, {%0,%1,%2,%3};"
        : "+f"(d[0]), "+f"(d[1]), "+f"(d[2]), "+f"(d[3])
        : "r"(a[0]), "r"(a[1]), "r"(a[2]), "r"(a[3]), "r"(b[0]), "r"(b[1]));
}

// ---------------------------------------------------------------------------
// Fused Kernel: GEMM CTAs (blockIdx.x < 32) + prototype CTAs (blockIdx.x == 32)
// (unchanged from R6 — banked working configuration)
// ---------------------------------------------------------------------------
#define KC      32
#define ASTR    36                      // smem row stride in floats (144B)
#define TILE_FL (64 * ASTR)             // floats per buffer

__global__ void __launch_bounds__(256, 1)
feat_gemm_kernel(const float* __restrict__ x,
                 const float* __restrict__ features,
                 const float* __restrict__ prototypes) {
    __shared__ __align__(16) float As[2][TILE_FL];
    __shared__ __align__(16) float Bs[2][TILE_FL];

    const int tid  = threadIdx.x;

    // ======================= prototype path =======================
    if (blockIdx.x == 32) {
        float (*t)[65] = (float(*)[65])&As[0][0];     // 64 x 65 tile
        const int p0 = blockIdx.y * 64;
        float spacc = 0.f;

        for (int fc = 0; fc < 4; fc++) {
            #pragma unroll
            for (int i = 0; i < 16; i++) {
                int idx = tid + i * 256;              // 0..4095
                int p = idx >> 6, f = idx & 63;
                t[p][f] = sigmoidf(prototypes[(size_t)(p0 + p) * NF + fc * 64 + f]);
            }
            __syncthreads();
            #pragma unroll
            for (int i = 0; i < 16; i++) {
                int idx = tid + i * 256;
                int f = idx >> 6, p = idx & 63;
                g_psigT[(size_t)(fc * 64 + f) * NP + p0 + p] = t[p][f];
            }
            if (tid < 64) {
                float s = 0.f;
                #pragma unroll 16
                for (int f = 0; f < 64; f++) s += t[tid][f];
                spacc += s;
            }
            __syncthreads();
        }
        if (tid < 64) g_Sp[p0 + tid] = spacc;
        return;
    }

    // ========================= GEMM path =========================
    const int wid  = tid >> 5;
    const int lane = tid & 31;
    const int b0 = blockIdx.x * 64;
    const int f0 = blockIdx.y * 64;
    const int m_off = (wid & 1) * 32;        // m in {0, 32}
    const int n_off = (wid >> 1) * 16;       // n in {0, 16, 32, 48}

    int lrow[2], lkq[2];
    #pragma unroll
    for (int i = 0; i < 2; i++) {
        int idx = tid + i * 256;
        lrow[i] = idx >> 3;                  // 0..63
        lkq[i]  = idx & 7;                   // float4 slot along k
    }

    const uint32_t sA = smem_u32(As);
    const uint32_t sB = smem_u32(Bs);
    const uint32_t a_off = (uint32_t)(((lane & 15) + m_off) * ASTR + ((lane >> 4) & 1) * 4) * 4;
    const uint32_t b_off = (uint32_t)((((lane & 7) + ((lane >> 4) & 1) * 8) + n_off) * ASTR
                                      + ((lane >> 3) & 1) * 4) * 4;

    float4 av[2], bv[2];
    #pragma unroll
    for (int i = 0; i < 2; i++) {
        av[i] = *(const float4*)&x[(size_t)(b0 + lrow[i]) * IN + lkq[i] * 4];
        bv[i] = *(const float4*)&features[(size_t)(f0 + lrow[i]) * IN + lkq[i] * 4];
    }

    float acc[2][2][4] = {};                 // [mt][nt][4]

    for (int c = 0; c < IN / KC; c++) {
        const int buf = c & 1;

        #pragma unroll
        for (int i = 0; i < 2; i++) {
            uint4 ua = make_uint4(tf32r(av[i].x), tf32r(av[i].y), tf32r(av[i].z), tf32r(av[i].w));
            uint4 ub = make_uint4(tf32r(bv[i].x), tf32r(bv[i].y), tf32r(bv[i].z), tf32r(bv[i].w));
            *(uint4*)&As[buf][lrow[i] * ASTR + lkq[i] * 4] = ua;
            *(uint4*)&Bs[buf][lrow[i] * ASTR + lkq[i] * 4] = ub;
        }
        __syncthreads();

        if (c + 1 < IN / KC) {
            const int k0 = (c + 1) * KC;
            #pragma unroll
            for (int i = 0; i < 2; i++) {
                av[i] = *(const float4*)&x[(size_t)(b0 + lrow[i]) * IN + k0 + lkq[i] * 4];
                bv[i] = *(const float4*)&features[(size_t)(f0 + lrow[i]) * IN + k0 + lkq[i] * 4];
            }
        }

        const uint32_t baseA = sA + (uint32_t)buf * TILE_FL * 4;
        const uint32_t baseB = sB + (uint32_t)buf * TILE_FL * 4;

        #pragma unroll
        for (int s = 0; s < 4; s++) {
            const uint32_t kb = (uint32_t)(s * 8) * 4;
            uint32_t aa[2][4], bb[4];
            ldsm_x4(aa[0][0], aa[0][1], aa[0][2], aa[0][3], baseA + a_off + kb);
            ldsm_x4(aa[1][0], aa[1][1], aa[1][2], aa[1][3], baseA + a_off + kb + 16 * ASTR * 4);
            ldsm_x4(bb[0], bb[1], bb[2], bb[3], baseB + b_off + kb);
            #pragma unroll
            for (int mt = 0; mt < 2; mt++)
                #pragma unroll
                for (int nt = 0; nt < 2; nt++)
                    mma_tf32(acc[mt][nt], aa[mt], &bb[nt * 2]);
        }
        __syncthreads();
    }

    // ---- epilogue: sigmoid, transpose-stage through smem, coalesced store ----
    float* Csm = &As[0][0];                  // 64 x 68 overlay
    #define CSTR 68
    __syncthreads();

    {
        const int mrow = m_off + (lane >> 2);
        const int ncol = n_off + 2 * (lane & 3);
        #pragma unroll
        for (int mt = 0; mt < 2; mt++) {
            #pragma unroll
            for (int nt = 0; nt < 2; nt++) {
                const int m = mrow + mt * 16;
                const int n = ncol + nt * 8;
                Csm[(n    ) * CSTR + m    ] = sigmoidf(acc[mt][nt][0]);
                Csm[(n + 1) * CSTR + m    ] = sigmoidf(acc[mt][nt][1]);
                Csm[(n    ) * CSTR + m + 8] = sigmoidf(acc[mt][nt][2]);
                Csm[(n + 1) * CSTR + m + 8] = sigmoidf(acc[mt][nt][3]);
            }
        }
    }
    __syncthreads();

    #pragma unroll
    for (int i = 0; i < 4; i++) {
        int idx = tid + i * 256;             // 0..1023
        int f = idx >> 4;
        int q = idx & 15;
        float4 v = *(float4*)&Csm[f * CSTR + q * 4];
        *(float4*)&g_xsigT[(size_t)(f0 + f) * BB + b0 + q * 4] = v;
    }

    if (tid < 64) {
        float s = 0.f;
        #pragma unroll 16
        for (int f = 0; f < 64; f++) s += Csm[f * CSTR + tid];
        g_SxP[blockIdx.y * BB + b0 + tid] = s;
    }
}

// ---------------------------------------------------------------------------
// Kernel C: Tversky core, v2 — 512 threads (16 warps -> 4 warps/SMSP).
// I[b,p] = sum_f min(xs, ps);  out = I / (I + a*(Sx-I) + b*(Sp-I) + eps) + bias
// 64(b) x 64(p) tile, each thread 4(b) x 2(p).  grid (32, 4) = 128 CTAs.
// Per k: LDS.128 (a, broadcast) + LDS.64 (p) + 8 FMNMX + 8 FADD.
// ---------------------------------------------------------------------------
__global__ void __launch_bounds__(512)
tversky_kernel(const float* __restrict__ bias,
               const float* __restrict__ alphap,
               const float* __restrict__ betap,
               float* __restrict__ out) {
    __shared__ float xs[32][64];   // [f][b]
    __shared__ float ps[32][64];   // [f][p]

    const int tid = threadIdx.x;
    const int tx = tid & 31;       // p direction (x2): p = p0 + tx*2 + j
    const int ty = tid >> 5;       // b direction (x4): b = b0 + ty*4 + i
    const int b0 = blockIdx.x * 64;
    const int p0 = blockIdx.y * 64;

    // loader mapping: 512 float4 per operand per chunk, 1 per thread
    const int lfr = tid >> 4;          // f-row 0..31
    const int lbc = (tid & 15) * 4;    // column (float4)

    float acc[4][2] = {};

    for (int f0 = 0; f0 < NF; f0 += 32) {
        *(float4*)&xs[lfr][lbc] = *(const float4*)&g_xsigT[(size_t)(f0 + lfr) * BB + b0 + lbc];
        *(float4*)&ps[lfr][lbc] = *(const float4*)&g_psigT[(size_t)(f0 + lfr) * NP + p0 + lbc];
        __syncthreads();

        #pragma unroll 8
        for (int k = 0; k < 32; k++) {
            float4 a = *(const float4*)&xs[k][ty * 4];
            float2 p = *(const float2*)&ps[k][tx * 2];
            float av[4] = {a.x, a.y, a.z, a.w};
            float pv[2] = {p.x, p.y};
            #pragma unroll
            for (int i = 0; i < 4; i++) {
                acc[i][0] += fminf(av[i], pv[0]);
                acc[i][1] += fminf(av[i], pv[1]);
            }
        }
        __syncthreads();
    }

    const float alpha = *alphap;
    const float beta  = *betap;

    float bi[2], spv[2];
    #pragma unroll
    for (int j = 0; j < 2; j++) {
        int p = p0 + tx * 2 + j;
        bi[j]  = bias[p];
        spv[j] = g_Sp[p];
    }

    #pragma unroll
    for (int i = 0; i < 4; i++) {
        int b = b0 + ty * 4 + i;
        float Sx = g_SxP[b] + g_SxP[BB + b] + g_SxP[2 * BB + b] + g_SxP[3 * BB + b];
        float2 o;
        #pragma unroll
        for (int j = 0; j < 2; j++) {
            float I = acc[i][j];
            float denom = I + alpha * (Sx - I) + beta * (spv[j] - I) + EPS;
            ((float*)&o)[j] = I / denom + bi[j];
        }
        *(float2*)&out[(size_t)b * NP + p0 + tx * 2] = o;
    }
}

// ---------------------------------------------------------------------------
// Launch. Inputs: x, features, prototypes, bias, alpha, beta.
// ---------------------------------------------------------------------------
extern "C" void kernel_launch(void* const* d_in, const int* in_sizes, int n_in,
                              void* d_out, int out_size) {
    const float* x          = (const float*)d_in[0];
    const float* features   = (const float*)d_in[1];
    const float* prototypes = (const float*)d_in[2];
    const float* bias       = (const float*)d_in[3];
    const float* alpha      = (const float*)d_in[4];
    const float* beta       = (const float*)d_in[5];
    float* out = (float*)d_out;

    feat_gemm_kernel<<<dim3(33, 4), 256>>>(x, features, prototypes);
    tversky_kernel<<<dim3(BB / 64, NP / 64), 512>>>(bias, alpha, beta, out);
}

// round 8
// speedup vs baseline: 1.0707x; 1.0518x over previous
#include <cuda_runtime.h>
#include <cstdint>

#define BB  2048
#define IN  512
#define NF  256
#define NP  256
#define EPS 1e-8f

// ---------------------------------------------------------------------------
// Device globals (allocation-free rule)
// ---------------------------------------------------------------------------
__device__ float g_xsigT[NF * BB];     // [f][b] sigmoid(x @ W^T), f-major
__device__ float g_psigT[NF * NP];     // [f][p] sigmoid(prototypes), f-major
__device__ float g_SxP[4 * BB];        // partial row sums of x_sig (per f-tile)
__device__ float g_Sp[NP];             // full row sums of p_sig

__device__ __forceinline__ float sigmoidf(float v) {
    return 1.0f / (1.0f + __expf(-v));
}

__device__ __forceinline__ uint32_t smem_u32(const void* p) {
    uint32_t a;
    asm("{ .reg .u64 t; cvta.to.shared.u64 t, %1; cvt.u32.u64 %0, t; }"
        : "=r"(a) : "l"(p));
    return a;
}

__device__ __forceinline__ uint32_t tf32r(float v) {
    uint32_t u;
    asm("cvt.rna.tf32.f32 %0, %1;" : "=r"(u) : "f"(v));
    return u;
}

__device__ __forceinline__ void ldsm_x4(uint32_t& r0, uint32_t& r1,
                                        uint32_t& r2, uint32_t& r3, uint32_t addr) {
    asm volatile("ldmatrix.sync.aligned.m8n8.x4.shared.b16 {%0,%1,%2,%3}, [%4];"
                 : "=r"(r0), "=r"(r1), "=r"(r2), "=r"(r3) : "r"(addr));
}

__device__ __forceinline__ void mma_tf32(float* d, const uint32_t* a, const uint32_t* b) {
    asm volatile(
        "mma.sync.aligned.m16n8k8.row.col.f32.tf32.tf32.f32 "
        "{%0,%1,%2,%3}, {%4,%5,%6,%7}, {%8,%9}, {%0,%1,%2,%3};"
        : "+f"(d[0]), "+f"(d[1]), "+f"(d[2]), "+f"(d[3])
        : "r"(a[0]), "r"(a[1]), "r"(a[2]), "r"(a[3]), "r"(b[0]), "r"(b[1]));
}

// ---------------------------------------------------------------------------
// Fused Kernel: GEMM CTAs (blockIdx.x < 32) + prototype CTAs (blockIdx.x == 32)
// GEMM: prefetch distance 2, single __syncthreads per K-chunk.
// ---------------------------------------------------------------------------
#define KC      32
#define ASTR    36                      // smem row stride in floats (144B)
#define TILE_FL (64 * ASTR)             // floats per buffer

__global__ void __launch_bounds__(256, 1)
feat_gemm_kernel(const float* __restrict__ x,
                 const float* __restrict__ features,
                 const float* __restrict__ prototypes) {
    __shared__ __align__(16) float As[2][TILE_FL];
    __shared__ __align__(16) float Bs[2][TILE_FL];

    const int tid  = threadIdx.x;

    // ======================= prototype path =======================
    if (blockIdx.x == 32) {
        float (*t)[65] = (float(*)[65])&As[0][0];     // 64 x 65 tile
        const int p0 = blockIdx.y * 64;
        float spacc = 0.f;

        for (int fc = 0; fc < 4; fc++) {
            #pragma unroll
            for (int i = 0; i < 16; i++) {
                int idx = tid + i * 256;              // 0..4095
                int p = idx >> 6, f = idx & 63;
                t[p][f] = sigmoidf(prototypes[(size_t)(p0 + p) * NF + fc * 64 + f]);
            }
            __syncthreads();
            #pragma unroll
            for (int i = 0; i < 16; i++) {
                int idx = tid + i * 256;
                int f = idx >> 6, p = idx & 63;
                g_psigT[(size_t)(fc * 64 + f) * NP + p0 + p] = t[p][f];
            }
            if (tid < 64) {
                float s = 0.f;
                #pragma unroll 16
                for (int f = 0; f < 64; f++) s += t[tid][f];
                spacc += s;
            }
            __syncthreads();
        }
        if (tid < 64) g_Sp[p0 + tid] = spacc;
        return;
    }

    // ========================= GEMM path =========================
    const int wid  = tid >> 5;
    const int lane = tid & 31;
    const int b0 = blockIdx.x * 64;
    const int f0 = blockIdx.y * 64;
    const int m_off = (wid & 1) * 32;        // m in {0, 32}
    const int n_off = (wid >> 1) * 16;       // n in {0, 16, 32, 48}

    int lrow[2], lkq[2];
    #pragma unroll
    for (int i = 0; i < 2; i++) {
        int idx = tid + i * 256;
        lrow[i] = idx >> 3;                  // 0..63
        lkq[i]  = idx & 7;                   // float4 slot along k
    }

    const uint32_t sA = smem_u32(As);
    const uint32_t sB = smem_u32(Bs);
    const uint32_t a_off = (uint32_t)(((lane & 15) + m_off) * ASTR + ((lane >> 4) & 1) * 4) * 4;
    const uint32_t b_off = (uint32_t)((((lane & 7) + ((lane >> 4) & 1) * 8) + n_off) * ASTR
                                      + ((lane >> 3) & 1) * 4) * 4;

    // prefetch reg sets for chunks 0 and 1 (distance-2 pipeline)
    float4 av[2][2], bv[2][2];
    #pragma unroll
    for (int s = 0; s < 2; s++)
        #pragma unroll
        for (int i = 0; i < 2; i++) {
            av[s][i] = *(const float4*)&x[(size_t)(b0 + lrow[i]) * IN + s * KC + lkq[i] * 4];
            bv[s][i] = *(const float4*)&features[(size_t)(f0 + lrow[i]) * IN + s * KC + lkq[i] * 4];
        }

    float acc[2][2][4] = {};                 // [mt][nt][4]

    #pragma unroll 2
    for (int c = 0; c < IN / KC; c++) {
        const int buf = c & 1;

        // store chunk c (held in reg set buf) to smem buf, with tf32 cvt
        #pragma unroll
        for (int i = 0; i < 2; i++) {
            uint4 ua = make_uint4(tf32r(av[buf][i].x), tf32r(av[buf][i].y),
                                  tf32r(av[buf][i].z), tf32r(av[buf][i].w));
            uint4 ub = make_uint4(tf32r(bv[buf][i].x), tf32r(bv[buf][i].y),
                                  tf32r(bv[buf][i].z), tf32r(bv[buf][i].w));
            *(uint4*)&As[buf][lrow[i] * ASTR + lkq[i] * 4] = ua;
            *(uint4*)&Bs[buf][lrow[i] * ASTR + lkq[i] * 4] = ub;
        }

        // prefetch chunk c+2 into the reg set just freed
        if (c + 2 < IN / KC) {
            const int k0 = (c + 2) * KC;
            #pragma unroll
            for (int i = 0; i < 2; i++) {
                av[buf][i] = *(const float4*)&x[(size_t)(b0 + lrow[i]) * IN + k0 + lkq[i] * 4];
                bv[buf][i] = *(const float4*)&features[(size_t)(f0 + lrow[i]) * IN + k0 + lkq[i] * 4];
            }
        }

        __syncthreads();                     // single sync per chunk

        const uint32_t baseA = sA + (uint32_t)buf * TILE_FL * 4;
        const uint32_t baseB = sB + (uint32_t)buf * TILE_FL * 4;

        #pragma unroll
        for (int s = 0; s < 4; s++) {
            const uint32_t kb = (uint32_t)(s * 8) * 4;
            uint32_t aa[2][4], bb[4];
            ldsm_x4(aa[0][0], aa[0][1], aa[0][2], aa[0][3], baseA + a_off + kb);
            ldsm_x4(aa[1][0], aa[1][1], aa[1][2], aa[1][3], baseA + a_off + kb + 16 * ASTR * 4);
            ldsm_x4(bb[0], bb[1], bb[2], bb[3], baseB + b_off + kb);
            #pragma unroll
            for (int mt = 0; mt < 2; mt++)
                #pragma unroll
                for (int nt = 0; nt < 2; nt++)
                    mma_tf32(acc[mt][nt], aa[mt], &bb[nt * 2]);
        }
    }

    // ---- epilogue: sigmoid, transpose-stage through smem, coalesced store ----
    float* Csm = &As[0][0];                  // 64 x 68 overlay
    #define CSTR 68
    __syncthreads();

    {
        const int mrow = m_off + (lane >> 2);
        const int ncol = n_off + 2 * (lane & 3);
        #pragma unroll
        for (int mt = 0; mt < 2; mt++) {
            #pragma unroll
            for (int nt = 0; nt < 2; nt++) {
                const int m = mrow + mt * 16;
                const int n = ncol + nt * 8;
                Csm[(n    ) * CSTR + m    ] = sigmoidf(acc[mt][nt][0]);
                Csm[(n + 1) * CSTR + m    ] = sigmoidf(acc[mt][nt][1]);
                Csm[(n    ) * CSTR + m + 8] = sigmoidf(acc[mt][nt][2]);
                Csm[(n + 1) * CSTR + m + 8] = sigmoidf(acc[mt][nt][3]);
            }
        }
    }
    __syncthreads();

    #pragma unroll
    for (int i = 0; i < 4; i++) {
        int idx = tid + i * 256;             // 0..1023
        int f = idx >> 4;
        int q = idx & 15;
        float4 v = *(float4*)&Csm[f * CSTR + q * 4];
        *(float4*)&g_xsigT[(size_t)(f0 + f) * BB + b0 + q * 4] = v;
    }

    if (tid < 64) {
        float s = 0.f;
        #pragma unroll 16
        for (int f = 0; f < 64; f++) s += Csm[f * CSTR + tid];
        g_SxP[blockIdx.y * BB + b0 + tid] = s;
    }
}

// ---------------------------------------------------------------------------
// Kernel C: Tversky core, v3 — square warp tiles, f-chunks of 64.
// 512 threads, 16 warps in a 4(b) x 4(p) grid; warp tile 16b x 16p;
// lane tile 4b x 2p (lane = lj*8 + li, lj = b, li = p).
// Per warp-k smem traffic after dedup: 64B (a) + 64B (p)  [was 16B + 256B].
// grid (32, 4) = 128 CTAs.
// ---------------------------------------------------------------------------
__global__ void __launch_bounds__(512)
tversky_kernel(const float* __restrict__ bias,
               const float* __restrict__ alphap,
               const float* __restrict__ betap,
               float* __restrict__ out) {
    __shared__ float xs[64][64];   // [f][b]  16 KB
    __shared__ float ps[64][64];   // [f][p]  16 KB

    const int tid = threadIdx.x;
    const int lane = tid & 31;
    const int wid  = tid >> 5;
    const int wi = wid & 3;        // warp p index
    const int wj = wid >> 2;       // warp b index
    const int li = lane & 7;       // lane p index (x2)
    const int lj = lane >> 3;      // lane b index (x4)
    const int b0 = blockIdx.x * 64;
    const int p0 = blockIdx.y * 64;

    const int bcol = wj * 16 + lj * 4;     // this thread's b offset in tile
    const int pcol = wi * 16 + li * 2;     // this thread's p offset in tile

    // loader mapping: 1024 float4 per array per chunk, 2 per thread
    const int fr0 = tid >> 4;              // rows 0..31
    const int fr1 = (tid + 512) >> 4;      // rows 32..63
    const int fq  = (tid & 15) * 4;

    // preload chunk 0 into regs
    float4 rx0 = *(const float4*)&g_xsigT[(size_t)fr0 * BB + b0 + fq];
    float4 rx1 = *(const float4*)&g_xsigT[(size_t)fr1 * BB + b0 + fq];
    float4 rp0 = *(const float4*)&g_psigT[(size_t)fr0 * NP + p0 + fq];
    float4 rp1 = *(const float4*)&g_psigT[(size_t)fr1 * NP + p0 + fq];

    float acc[4][2] = {};

    #pragma unroll
    for (int c = 0; c < 4; c++) {
        if (c > 0) __syncthreads();        // previous chunk reads done
        *(float4*)&xs[fr0][fq] = rx0;
        *(float4*)&xs[fr1][fq] = rx1;
        *(float4*)&ps[fr0][fq] = rp0;
        *(float4*)&ps[fr1][fq] = rp1;

        if (c < 3) {                       // preload next chunk (L2-resident)
            const int f0n = (c + 1) * 64;
            rx0 = *(const float4*)&g_xsigT[(size_t)(f0n + fr0) * BB + b0 + fq];
            rx1 = *(const float4*)&g_xsigT[(size_t)(f0n + fr1) * BB + b0 + fq];
            rp0 = *(const float4*)&g_psigT[(size_t)(f0n + fr0) * NP + p0 + fq];
            rp1 = *(const float4*)&g_psigT[(size_t)(f0n + fr1) * NP + p0 + fq];
        }
        __syncthreads();

        #pragma unroll 8
        for (int k = 0; k < 64; k++) {
            float4 a = *(const float4*)&xs[k][bcol];
            float2 p = *(const float2*)&ps[k][pcol];
            float av[4] = {a.x, a.y, a.z, a.w};
            #pragma unroll
            for (int i = 0; i < 4; i++) {
                acc[i][0] += fminf(av[i], p.x);
                acc[i][1] += fminf(av[i], p.y);
            }
        }
    }

    const float alpha = *alphap;
    const float beta  = *betap;

    float bi[2], spv[2];
    #pragma unroll
    for (int j = 0; j < 2; j++) {
        int p = p0 + pcol + j;
        bi[j]  = bias[p];
        spv[j] = g_Sp[p];
    }

    #pragma unroll
    for (int i = 0; i < 4; i++) {
        int b = b0 + bcol + i;
        float Sx = g_SxP[b] + g_SxP[BB + b] + g_SxP[2 * BB + b] + g_SxP[3 * BB + b];
        float2 o;
        #pragma unroll
        for (int j = 0; j < 2; j++) {
            float I = acc[i][j];
            float denom = I + alpha * (Sx - I) + beta * (spv[j] - I) + EPS;
            ((float*)&o)[j] = I / denom + bi[j];
        }
        *(float2*)&out[(size_t)b * NP + p0 + pcol] = o;
    }
}

// ---------------------------------------------------------------------------
// Launch. Inputs: x, features, prototypes, bias, alpha, beta.
// ---------------------------------------------------------------------------
extern "C" void kernel_launch(void* const* d_in, const int* in_sizes, int n_in,
                              void* d_out, int out_size) {
    const float* x          = (const float*)d_in[0];
    const float* features   = (const float*)d_in[1];
    const float* prototypes = (const float*)d_in[2];
    const float* bias       = (const float*)d_in[3];
    const float* alpha      = (const float*)d_in[4];
    const float* beta       = (const float*)d_in[5];
    float* out = (float*)d_out;

    feat_gemm_kernel<<<dim3(33, 4), 256>>>(x, features, prototypes);
    tversky_kernel<<<dim3(BB / 64, NP / 64), 512>>>(bias, alpha, beta, out);
}